// round 16
// baseline (speedup 1.0000x reference)
#include <cuda_runtime.h>
#include <math.h>
#include <stdint.h>

// ---------------- problem constants ----------------
#define D1      512
#define D2      1024
#define SEQLEN  4096
#define CHUNK   256
#define NCHUNK  16
#define BATCH   4
#define NROWS   (BATCH*CHUNK)          // 1024 rows per chunk
#define TOTROWS (BATCH*SEQLEN)         // 16384
#define LOSS_SCALE (2.0f/((float)NROWS*(float)D1))

// ---------------- device scratch ----------------
__device__ float g_W1 [D1*D2];
__device__ float g_W2a[D2*D1];         // W2 ping
__device__ float g_W2b[D2*D1];         // W2 pong
__device__ float g_W2Ta[D1*D2];        // W2^T ping  [D1][D2]
__device__ float g_W2Tb[D1*D2];        // W2^T pong
__device__ float g_S1 [D1*D2];
__device__ float g_S2 [D2*D1];
__device__ float g_WKV[D1*D2];
__device__ float g_kv [NCHUNK*NROWS*D2];   // chunk-major: [c][b][r][D2]; 0..511=k, 512..1023=v
__device__ float g_kT [NCHUNK*D1*NROWS];   // k^T per chunk: [c][d1][row]
__device__ float g_h  [NROWS*D2];
__device__ float g_a  [NROWS*D2];
__device__ float g_aT [D2*NROWS];          // a^T for g2 fast path
__device__ float g_dp [NROWS*D1];
__device__ float g_dh [NROWS*D2];
__device__ float g_q  [TOTROWS*D1];
__device__ float g_aq [TOTROWS*D2];

// grid barrier state (self-resetting across uses/replays)
__device__ unsigned g_bar_cnt = 0;
__device__ volatile unsigned g_bar_gen = 0;

// ---------------- math helpers ----------------
__device__ __forceinline__ float gelu_f(float x) {
    return 0.5f * x * (1.0f + erff(x * 0.70710678118654752f));
}
__device__ __forceinline__ float gelu_grad(float x) {
    float cdf = 0.5f * (1.0f + erff(x * 0.70710678118654752f));
    float pdf = 0.3989422804014327f * expf(-0.5f * x * x);
    return cdf + x * pdf;
}
__device__ __forceinline__ float sigmoid_f(float x) { return 1.0f / (1.0f + expf(-x)); }

__device__ __forceinline__ void split_tf32(float v, uint32_t& hi, uint32_t& lo) {
    uint32_t h;
    asm("cvt.rna.tf32.f32 %0, %1;" : "=r"(h) : "f"(v));
    float lf = v - __uint_as_float(h);
    asm("cvt.rna.tf32.f32 %0, %1;" : "=r"(lo) : "f"(lf));
    hi = h;
}
__device__ __forceinline__ void mma_tf32(float* c, const uint32_t* a, const uint32_t* b) {
    asm volatile(
        "mma.sync.aligned.m16n8k8.row.col.f32.tf32.tf32.f32 "
        "{%0,%1,%2,%3}, {%4,%5,%6,%7}, {%8,%9}, {%0,%1,%2,%3};"
        : "+f"(c[0]), "+f"(c[1]), "+f"(c[2]), "+f"(c[3])
        : "r"(a[0]), "r"(a[1]), "r"(a[2]), "r"(a[3]), "r"(b[0]), "r"(b[1]));
}

// cp.async helpers
__device__ __forceinline__ void cp16(void* s, const void* g) {
    uint32_t sa = (uint32_t)__cvta_generic_to_shared(s);
    asm volatile("cp.async.ca.shared.global [%0], [%1], 16;\n" :: "r"(sa), "l"(g));
}
__device__ __forceinline__ void cp4(void* s, const void* g) {
    uint32_t sa = (uint32_t)__cvta_generic_to_shared(s);
    asm volatile("cp.async.ca.shared.global [%0], [%1], 4;\n" :: "r"(sa), "l"(g));
}
#define CP_COMMIT() asm volatile("cp.async.commit_group;\n" ::: "memory")
#define CP_WAIT(n)  asm volatile("cp.async.wait_group %0;\n" :: "n"(n) : "memory")

// ---------------- grid barrier ----------------
// SAFE ONLY because grid (128 CTAs) <= SM count (148): every CTA is resident
// even at 1 CTA/SM, so the spin always makes progress.
#define GRID_CTAS 128u
__device__ __forceinline__ void grid_barrier() {
    __syncthreads();
    if (threadIdx.x == 0) {
        __threadfence();
        unsigned gen = g_bar_gen;
        if (atomicAdd(&g_bar_cnt, 1u) == GRID_CTAS - 1u) {
            g_bar_cnt = 0;
            __threadfence();
            g_bar_gen = gen + 1u;
        } else {
            while (g_bar_gen == gen) { __nanosleep(64); }
            __threadfence();
        }
    }
    __syncthreads();
}

// ---------------- init ----------------
__global__ void init_kernel(const float* __restrict__ mw1, const float* __restrict__ mw2,
                            const float* __restrict__ wk,  const float* __restrict__ wv) {
    int i = blockIdx.x * blockDim.x + threadIdx.x;
    if (i < D1 * D2) {
        g_W1[i]  = mw1[i];  g_S1[i] = 0.0f;
        g_W2a[i] = mw2[i];  g_S2[i] = 0.0f;
        {   // W2^T init: mw2 is [D2][D1]; W2T[n][m] = mw2[m][n]
            int m = i / D1, n = i % D1;
            g_W2Ta[(size_t)n * D2 + m] = mw2[i];
        }
        int d = i / D2, j = i % D2;
        g_WKV[i] = (j < D1) ? wk[d * D1 + j] : wv[d * D1 + (j - D1)];
    }
}

// ---------------- tiling ----------------
#define BM 64
#define BN 64
#define BK 32
#define APAD 4   // A row = 36 words
#define BPAD 8   // B row = 72 words
#define SA_WORDS (2*BM*(BK+APAD))
#define SB_WORDS (2*BK*(BN+BPAD))

// ---------------- tile GEMM device function (R13-proven body) ----------------
// op(A)[M,K] * op(B)[K,N] for one 64x64 tile at (row0,col0)
// EPI: 0 C=acc | 1 C=acc, aux3=gelu(acc) | 2 C=(acc-aux1)*LOSS_SCALE | 3 C=acc*gelu'(aux1)
//      4 S(aux3)=decay*S-lr*acc; Wnew(aux4)=(1-a)*Wold(aux1)+S; auxT?=Wnew^T
//      5 C=gelu(acc) | 6 kv chunk-major permute; auxT?=k^T
//      7 C=acc; aux3=gelu(acc); auxT[n*NROWS+m]=gelu(acc)   (h stage: a and a^T)
template<bool TA, bool TB, int EPI>
__device__ __forceinline__ void gemm_tile(
        float* sAraw, float* sBraw, int row0, int col0,
        const float* __restrict__ A, const float* __restrict__ B, float* __restrict__ C,
        int K, int lda, int ldb, int ldc, int ldaux,
        const float* __restrict__ aux1, float* __restrict__ aux3, float* __restrict__ aux4,
        float* __restrict__ auxT,
        float alpha, float lr, float decay) {
    auto As = reinterpret_cast<float (*)[BM][BK + APAD]>(sAraw);
    auto Bs = reinterpret_cast<float (*)[BK][BN + BPAD]>(sBraw);

    const int t    = threadIdx.x;
    const int lane = t & 31;
    const int warp = t >> 5;
    const int warpRow = (warp >> 1) * 32;
    const int warpCol = (warp & 1) * 32;
    const int g  = lane >> 2;
    const int t4 = lane & 3;

    auto stage = [&](int b, int k0) {
        #pragma unroll
        for (int it = 0; it < 4; it++) {
            int f = t + it * 128;
            if constexpr (!TA) {
                int m = f >> 3, kk0 = (f & 7) * 4;
                cp16(&As[b][m][kk0], &A[(size_t)(row0 + m) * lda + (k0 + kk0)]);
            } else {
                int m0 = (f & 15) * 4, kk = f >> 4;
                const float* src = &A[(size_t)(k0 + kk) * lda + (row0 + m0)];
                cp4(&As[b][m0 + 0][kk], src + 0);
                cp4(&As[b][m0 + 1][kk], src + 1);
                cp4(&As[b][m0 + 2][kk], src + 2);
                cp4(&As[b][m0 + 3][kk], src + 3);
            }
        }
        #pragma unroll
        for (int it = 0; it < 4; it++) {
            int f = t + it * 128;
            if constexpr (!TB) {
                int n0 = (f & 15) * 4, kk = f >> 4;
                cp16(&Bs[b][kk][n0], &B[(size_t)(k0 + kk) * ldb + (col0 + n0)]);
            } else {
                int kk0 = (f & 7) * 4, n = f >> 3;
                const float* src = &B[(size_t)(col0 + n) * ldb + (k0 + kk0)];
                cp4(&Bs[b][kk0 + 0][n], src + 0);
                cp4(&Bs[b][kk0 + 1][n], src + 1);
                cp4(&Bs[b][kk0 + 2][n], src + 2);
                cp4(&Bs[b][kk0 + 3][n], src + 3);
            }
        }
    };

    float acc[2][4][4];
    #pragma unroll
    for (int i = 0; i < 2; i++)
        #pragma unroll
        for (int j = 0; j < 4; j++)
            #pragma unroll
            for (int r = 0; r < 4; r++) acc[i][j][r] = 0.0f;

    const int KITER = K / BK;
    stage(0, 0);
    CP_COMMIT();
    int buf = 0;
    for (int it = 0; it < KITER; ++it) {
        if (it + 1 < KITER) {
            stage(buf ^ 1, (it + 1) * BK);
            CP_COMMIT();
            CP_WAIT(1);
        } else {
            CP_WAIT(0);
        }
        __syncthreads();

        #pragma unroll
        for (int ks = 0; ks < 4; ks++) {
            const int kc = ks * 8 + t4;
            uint32_t ah[2][4], al[2][4], bh[4][2], bl[4][2];
            #pragma unroll
            for (int i = 0; i < 2; i++) {
                const int mB = warpRow + i * 16;
                split_tf32(As[buf][mB + g    ][kc    ], ah[i][0], al[i][0]);
                split_tf32(As[buf][mB + g + 8][kc    ], ah[i][1], al[i][1]);
                split_tf32(As[buf][mB + g    ][kc + 4], ah[i][2], al[i][2]);
                split_tf32(As[buf][mB + g + 8][kc + 4], ah[i][3], al[i][3]);
            }
            #pragma unroll
            for (int j = 0; j < 4; j++) {
                const int nB = warpCol + j * 8 + g;
                split_tf32(Bs[buf][kc    ][nB], bh[j][0], bl[j][0]);
                split_tf32(Bs[buf][kc + 4][nB], bh[j][1], bl[j][1]);
            }
            #pragma unroll
            for (int i = 0; i < 2; i++)
                #pragma unroll
                for (int j = 0; j < 4; j++) mma_tf32(acc[i][j], ah[i], bh[j]);
            #pragma unroll
            for (int i = 0; i < 2; i++)
                #pragma unroll
                for (int j = 0; j < 4; j++) mma_tf32(acc[i][j], ah[i], bl[j]);
            #pragma unroll
            for (int i = 0; i < 2; i++)
                #pragma unroll
                for (int j = 0; j < 4; j++) mma_tf32(acc[i][j], al[i], bh[j]);
        }
        __syncthreads();
        buf ^= 1;
    }

    #pragma unroll
    for (int i = 0; i < 2; i++) {
        const int rA = row0 + warpRow + i * 16 + g;
        #pragma unroll
        for (int j = 0; j < 4; j++) {
            const int cA = col0 + warpCol + j * 8 + 2 * t4;
            #pragma unroll
            for (int r = 0; r < 4; r++) {
                const int m = rA + (r >= 2 ? 8 : 0);
                const int n = cA + (r & 1);
                const size_t ci = (size_t)m * ldc + n;
                const float v = acc[i][j][r];
                if constexpr (EPI == 0) {
                    C[ci] = v;
                } else if constexpr (EPI == 1) {
                    C[ci] = v;
                    aux3[ci] = gelu_f(v);
                } else if constexpr (EPI == 2) {
                    C[ci] = (v - aux1[(size_t)m * ldaux + n]) * LOSS_SCALE;
                } else if constexpr (EPI == 3) {
                    C[ci] = v * gelu_grad(aux1[(size_t)m * ldaux + n]);
                } else if constexpr (EPI == 4) {
                    float s = decay * aux3[ci] - lr * v;
                    aux3[ci] = s;                                  // S update (in place)
                    float w = (1.0f - alpha) * aux1[ci] + s;       // Wnew = (1-a)*Wold + S
                    aux4[ci] = w;
                    if (auxT) auxT[(size_t)n * ldaux + m] = w;     // Wnew^T
                } else if constexpr (EPI == 5) {
                    C[ci] = gelu_f(v);
                } else if constexpr (EPI == 6) {
                    // m = b*4096 + c*256 + r  ->  out row = (c*BATCH+b)*256 + r
                    int bb = m >> 12;
                    int cc = (m >> 8) & (NCHUNK - 1);
                    int rr = m & (CHUNK - 1);
                    int lrow = bb * CHUNK + rr;                 // chunk-local row
                    size_t orow = ((size_t)cc * BATCH << 8) + ((size_t)bb << 8) + rr;
                    C[orow * ldc + n] = v;
                    if (n < D1) auxT[((size_t)cc * D1 + n) * NROWS + lrow] = v;  // k^T
                } else if constexpr (EPI == 7) {
                    C[ci] = v;
                    float gv = gelu_f(v);
                    aux3[ci] = gv;                               // a
                    auxT[(size_t)n * NROWS + m] = gv;            // a^T
                }
            }
        }
    }
}

// ---------------- standalone GEMM kernel (kv / q / aq / out) ----------------
template<bool TA, bool TB, int EPI>
__global__ __launch_bounds__(128)
void gemm3(const float* __restrict__ A, const float* __restrict__ B, float* __restrict__ C,
           int K, int lda, int ldb, int ldc, int ldaux,
           const float* __restrict__ aux1, float* __restrict__ aux3, float* __restrict__ aux4,
           float* __restrict__ auxT,
           const float* __restrict__ pa, const float* __restrict__ pl, const float* __restrict__ pd,
           int cidx) {
    __shared__ float sA[SA_WORDS];
    __shared__ float sB[SB_WORDS];
    int by = blockIdx.y;
    if constexpr (EPI == 6) by = (by >> 2) * 64 + cidx * 4 + (by & 3);  // rows of chunk cidx
    float alpha = 0.f, lr = 0.f, decay = 0.f;
    if constexpr (EPI == 4) {
        alpha = sigmoid_f(*pa);
        lr    = sigmoid_f(*pl);
        decay = sigmoid_f(*pd);
    }
    gemm_tile<TA, TB, EPI>(sA, sB, by * BM, blockIdx.x * BN,
                           A, B, C, K, lda, ldb, ldc, ldaux,
                           aux1, aux3, aux4, auxT, alpha, lr, decay);
}

// ---------------- per-chunk megakernel: h -> dpred -> dh -> g1,g2 ----------------
// Grid MUST be GRID_CTAS (=128) <= SM count for the grid barrier to be safe.
__global__ __launch_bounds__(128)
void chunk_step_kernel(const float* __restrict__ KVc, const float* __restrict__ KTc,
                       float* __restrict__ W1, float* __restrict__ S1,
                       const float* __restrict__ W2o, float* __restrict__ W2n,
                       const float* __restrict__ W2To, float* __restrict__ W2Tn,
                       float* __restrict__ S2,
                       float* __restrict__ H, float* __restrict__ Abuf, float* __restrict__ AT,
                       float* __restrict__ DP, float* __restrict__ DH,
                       const float* __restrict__ pa, const float* __restrict__ pl,
                       const float* __restrict__ pd) {
    __shared__ float sA[SA_WORDS];
    __shared__ float sB[SB_WORDS];
    const int cta = (int)blockIdx.x;
    const float alpha = sigmoid_f(*pa);
    const float lr    = sigmoid_f(*pl);
    const float decay = sigmoid_f(*pd);

    // S1: h = k @ W1 ; a = gelu(h) ; a^T   (256 tiles over 16x16; 2 per CTA)
    #pragma unroll
    for (int p = 0; p < 2; p++) {
        int tid = cta + p * 128;
        gemm_tile<false, false, 7>(sA, sB, (tid >> 4) * BM, (tid & 15) * BN,
            KVc, W1, H, D1, D2, D2, D2, 0, nullptr, Abuf, nullptr, AT, alpha, lr, decay);
    }
    grid_barrier();

    // S2: dpred = (a @ W2o - v)*LS   (128 tiles over 16x8; 1 per CTA)
    gemm_tile<false, false, 2>(sA, sB, (cta >> 3) * BM, (cta & 7) * BN,
        Abuf, W2o, DP, D2, D2, D1, D1, D2, KVc + D1, nullptr, nullptr, nullptr,
        alpha, lr, decay);
    grid_barrier();

    // S3: dh = (dpred @ W2T) * gelu'(h)   (256 tiles; 2 per CTA)
    #pragma unroll
    for (int p = 0; p < 2; p++) {
        int tid = cta + p * 128;
        gemm_tile<false, false, 3>(sA, sB, (tid >> 4) * BM, (tid & 15) * BN,
            DP, W2To, DH, D1, D1, D2, D2, D2, H, nullptr, nullptr, nullptr,
            alpha, lr, decay);
    }
    grid_barrier();

    // S4: g1 (128 tiles over 8x16) then g2 (128 tiles over 16x8); 2 per CTA
    #pragma unroll
    for (int p = 0; p < 2; p++) {
        const bool isG1 = (p == 0);
        const int row0 = isG1 ? (cta >> 4) * BM : (cta >> 3) * BM;
        const int col0 = isG1 ? (cta & 15) * BN : (cta & 7) * BN;
        const float* A4 = isG1 ? KTc : AT;
        const float* B4 = isG1 ? DH  : DP;
        const int   lda4 = NROWS;
        const int   ldb4 = isG1 ? D2 : D1;
        const int   ldc4 = isG1 ? D2 : D1;
        const float* Wo4 = isG1 ? W1 : W2o;
        float* S4p = isG1 ? S1 : S2;
        float* Wn4 = isG1 ? W1 : W2n;
        float* T4  = isG1 ? nullptr : W2Tn;
        gemm_tile<false, false, 4>(sA, sB, row0, col0,
            A4, B4, nullptr, NROWS, lda4, ldb4, ldc4, D2, Wo4, S4p, Wn4, T4,
            alpha, lr, decay);
    }
}

// ---------------- host driver ----------------
extern "C" void kernel_launch(void* const* d_in, const int* in_sizes, int n_in,
                              void* d_out, int out_size) {
    const float* x     = (const float*)d_in[0];
    const float* w_q   = (const float*)d_in[1];
    const float* w_k   = (const float*)d_in[2];
    const float* w_v   = (const float*)d_in[3];
    const float* mw1   = (const float*)d_in[4];
    const float* mw2   = (const float*)d_in[5];
    const float* p_al  = (const float*)d_in[6];
    const float* p_lr  = (const float*)d_in[7];
    const float* p_dec = (const float*)d_in[8];
    float* out = (float*)d_out;

    float *W1, *W2a, *W2b, *W2Ta, *W2Tb, *S1, *S2, *WKV, *KV, *KT, *H, *Abuf, *AT, *DP, *DH, *Q, *AQ;
    cudaGetSymbolAddress((void**)&W1,   g_W1);
    cudaGetSymbolAddress((void**)&W2a,  g_W2a);
    cudaGetSymbolAddress((void**)&W2b,  g_W2b);
    cudaGetSymbolAddress((void**)&W2Ta, g_W2Ta);
    cudaGetSymbolAddress((void**)&W2Tb, g_W2Tb);
    cudaGetSymbolAddress((void**)&S1,   g_S1);
    cudaGetSymbolAddress((void**)&S2,   g_S2);
    cudaGetSymbolAddress((void**)&WKV,  g_WKV);
    cudaGetSymbolAddress((void**)&KV,   g_kv);
    cudaGetSymbolAddress((void**)&KT,   g_kT);
    cudaGetSymbolAddress((void**)&H,    g_h);
    cudaGetSymbolAddress((void**)&Abuf, g_a);
    cudaGetSymbolAddress((void**)&AT,   g_aT);
    cudaGetSymbolAddress((void**)&DP,   g_dp);
    cudaGetSymbolAddress((void**)&DH,   g_dh);
    cudaGetSymbolAddress((void**)&Q,    g_q);
    cudaGetSymbolAddress((void**)&AQ,   g_aq);
    float* W2buf[2]  = { W2a,  W2b  };
    float* W2Tbuf[2] = { W2Ta, W2Tb };

    // one-time resources (handles only; created outside graph capture)
    static cudaStream_t s2 = nullptr;
    static cudaEvent_t evFork, evQ, evKV[NCHUNK];
    if (!s2) {
        cudaStreamCreateWithFlags(&s2, cudaStreamNonBlocking);
        cudaEventCreateWithFlags(&evFork, cudaEventDisableTiming);
        cudaEventCreateWithFlags(&evQ,    cudaEventDisableTiming);
        for (int i = 0; i < NCHUNK; i++)
            cudaEventCreateWithFlags(&evKV[i], cudaEventDisableTiming);
    }

    init_kernel<<<(D1 * D2 + 255) / 256, 256>>>(mw1, mw2, w_k, w_v);

    // kv for chunk 0 on main stream (chain needs it immediately); also writes k^T chunk 0
    gemm3<false, false, 6><<<dim3(D2 / BN, 16), 128>>>(
        x, WKV, KV, D1, D1, D2, D2, 0, nullptr, nullptr, nullptr, KT,
        nullptr, nullptr, nullptr, 0);

    // fork side stream: kv chunks 1..15 + q, concurrent with the chain
    cudaEventRecord(evFork, 0);
    cudaStreamWaitEvent(s2, evFork, 0);
    for (int c = 1; c < NCHUNK; c++) {
        gemm3<false, false, 6><<<dim3(D2 / BN, 16), 128, 0, s2>>>(
            x, WKV, KV, D1, D1, D2, D2, 0, nullptr, nullptr, nullptr, KT,
            nullptr, nullptr, nullptr, c);
        cudaEventRecord(evKV[c], s2);
    }
    gemm3<false, false, 0><<<dim3(D1 / BN, TOTROWS / BM), 128, 0, s2>>>(
        x, w_q, Q, D1, D1, D1, D1, 0, nullptr, nullptr, nullptr, nullptr,
        nullptr, nullptr, nullptr, 0);
    cudaEventRecord(evQ, s2);

    // chain: one megakernel per chunk (all intra-chunk deps via grid barriers)
    for (int c = 0; c < NCHUNK; c++) {
        const float* KVc = KV + (size_t)c * NROWS * D2;
        const float* KTc = KT + (size_t)c * D1 * NROWS;
        float* W2o  = W2buf [c & 1];
        float* W2n  = W2buf [(c + 1) & 1];
        float* W2To = W2Tbuf[c & 1];
        float* W2Tn = W2Tbuf[(c + 1) & 1];

        if (c > 0) cudaStreamWaitEvent(0, evKV[c], 0);   // kv + k^T for this chunk ready

        chunk_step_kernel<<<GRID_CTAS, 128>>>(
            KVc, KTc, W1, S1, W2o, W2n, W2To, W2Tn, S2,
            H, Abuf, AT, DP, DH, p_al, p_lr, p_dec);
    }

    // join with q
    cudaStreamWaitEvent(0, evQ, 0);

    // aq = gelu(q @ W1)
    gemm3<false, false, 5><<<dim3(D2 / BN, TOTROWS / BM), 128>>>(
        Q, W1, AQ, D1, D1, D2, D2, 0, nullptr, nullptr, nullptr, nullptr,
        nullptr, nullptr, nullptr, 0);

    // out = aq @ W2_final
    gemm3<false, false, 0><<<dim3(D1 / BN, TOTROWS / BM), 128>>>(
        AQ, W2buf[0], out, D2, D2, D1, D1, 0, nullptr, nullptr, nullptr, nullptr,
        nullptr, nullptr, nullptr, 0);
}